// round 1
// baseline (speedup 1.0000x reference)
#include <cuda_runtime.h>
#include <cuda_bf16.h>
#include <cstdint>

#define BB 4
#define CC 256
#define HH 128
#define WW 128
#define HWN 16384
#define PP 2048
#define THRV 0.8f

// ---------------- scratch (no allocations allowed) ----------------
__device__ float g_G[BB * PP * CC];   // gathered features [B][P][C]
__device__ float g_Z[BB * PP * CC];   // after GCN stage 1 [B][P][C]
__device__ float g_WT[CC * CC];       // Wwg transposed: WT[c][d] = Wwg[d][c]
__device__ int   g_idx[BB * PP];      // topk indices per batch

// ---------------- top-k: full bitonic sort of 16384 u64 keys -------
// key = (float_bits(value) << 32) | (uint32)(~index)  -> descending sort
// gives descending by value, ascending index on ties (== jax.lax.top_k)
__global__ void topk_kernel(const float* __restrict__ edge, int* __restrict__ idx_out)
{
    extern __shared__ unsigned long long keys[];
    const int b = blockIdx.x;
    const float* e = edge + b * HWN;

    for (int i = threadIdx.x; i < HWN; i += blockDim.x) {
        float v = e[i];
        if (v < THRV) v = 0.0f;
        unsigned int fb = __float_as_uint(v);       // v >= 0 -> bits monotonic
        keys[i] = ((unsigned long long)fb << 32) | (unsigned int)(~i);
    }
    __syncthreads();

    for (int k = 2; k <= HWN; k <<= 1) {
        for (int j = k >> 1; j > 0; j >>= 1) {
            for (int i = threadIdx.x; i < HWN; i += blockDim.x) {
                int ixj = i ^ j;
                if (ixj > i) {
                    unsigned long long a = keys[i];
                    unsigned long long c = keys[ixj];
                    bool up = (i & k) == 0;
                    // descending sort comparator
                    if (up ? (a < c) : (a > c)) {
                        keys[i] = c;
                        keys[ixj] = a;
                    }
                }
            }
            __syncthreads();
        }
    }

    for (int p = threadIdx.x; p < PP; p += blockDim.x) {
        unsigned int lo = (unsigned int)(keys[p] & 0xFFFFFFFFu);
        idx_out[b * PP + p] = (int)(~lo);
    }
}

// ---------------- gather: G[b][p][c] = x[b][c][idx[b][p]] ----------
__global__ void gather_kernel(const float* __restrict__ x,
                              const int* __restrict__ idx,
                              float* __restrict__ G)
{
    int b = blockIdx.y;
    int p = blockIdx.x;
    int c = threadIdx.x;
    int j = idx[b * PP + p];
    G[(b * PP + p) * CC + c] = x[((b * CC) + c) * HWN + j];
}

// ---------------- transpose Wwg [d][c] -> WT [c][d] ----------------
__global__ void transpose_wg(const float* __restrict__ W, float* __restrict__ WT)
{
    int d = blockIdx.x;
    int c = threadIdx.x;
    WT[c * CC + d] = W[d * CC + c];
}

// ---------------- SGEMM 128x128x8, 256 thr, 8x8 micro --------------
#define BM 128
#define BN 128
#define BK 8
#define TM 8
#define TN 8

// GEMM1: Z[b][o][c] = relu( (sum_p Wadj[o][p] * G[b][p][c]) * inv*ga[o] + be[o] ) + G[b][o][c]
__global__ __launch_bounds__(256) void gemm1_kernel(
    const float* __restrict__ A,     // Wadj [2048][2048]
    const float* __restrict__ Gm,    // [B][P][C]
    const float* __restrict__ ga,
    const float* __restrict__ be,
    float* __restrict__ Z)
{
    const int b  = blockIdx.z;
    const int m0 = blockIdx.y * BM;  // o
    const int n0 = blockIdx.x * BN;  // c
    const float* Bmat = Gm + (size_t)b * PP * CC;   // [P][C], ldb = 256
    float* Cout = Z + (size_t)b * PP * CC;

    __shared__ float As[BK][BM + 4];
    __shared__ float Bs[BK][BN];

    const int t  = threadIdx.x;
    const int tx = t & 15;
    const int ty = t >> 4;

    float acc[TM][TN];
    #pragma unroll
    for (int i = 0; i < TM; i++)
        #pragma unroll
        for (int j = 0; j < TN; j++) acc[i][j] = 0.0f;

    const int lda = PP;   // 2048
    const int ldb = CC;   // 256

    for (int k0 = 0; k0 < PP; k0 += BK) {
        {   // A tile: As[k][m], 128x8 = 1024 floats, 4/thread
            int l = t * 4;
            int m  = l >> 3;
            int kk = l & 7;
            float4 v = *(const float4*)(A + (size_t)(m0 + m) * lda + k0 + kk);
            As[kk + 0][m] = v.x;
            As[kk + 1][m] = v.y;
            As[kk + 2][m] = v.z;
            As[kk + 3][m] = v.w;
        }
        {   // B tile: Bs[k][n], 8x128
            int l = t * 4;
            int kk = l >> 7;
            int n  = l & 127;
            float4 v = *(const float4*)(Bmat + (size_t)(k0 + kk) * ldb + n0 + n);
            *(float4*)&Bs[kk][n] = v;
        }
        __syncthreads();

        #pragma unroll
        for (int kk = 0; kk < BK; kk++) {
            float af[TM], bf[TN];
            #pragma unroll
            for (int i = 0; i < TM; i++) af[i] = As[kk][ty * TM + i];
            #pragma unroll
            for (int j = 0; j < TN; j++) bf[j] = Bs[kk][tx * TN + j];
            #pragma unroll
            for (int i = 0; i < TM; i++)
                #pragma unroll
                for (int j = 0; j < TN; j++)
                    acc[i][j] = fmaf(af[i], bf[j], acc[i][j]);
        }
        __syncthreads();
    }

    const float inv = rsqrtf(1.0f + 1e-5f);
    #pragma unroll
    for (int i = 0; i < TM; i++) {
        int o = m0 + ty * TM + i;
        float s  = inv * ga[o];
        float bb = be[o];
        #pragma unroll
        for (int j = 0; j < TN; j++) {
            int c = n0 + tx * TN + j;
            float v = fmaf(acc[i][j], s, bb);
            v = fmaxf(v, 0.0f) + Gm[((size_t)b * PP + o) * CC + c];
            Cout[(size_t)o * CC + c] = v;
        }
    }
}

// GEMM2 + scatter: out[b][d][idx[b][p]] = relu( (sum_c Z[b][p][c] * WT[c][d]) * inv*gw[d] + bw[d] )
__global__ __launch_bounds__(256) void gemm2_kernel(
    const float* __restrict__ Zm,    // [B][P][C]  (A: M=p, K=c)
    const float* __restrict__ WT,    // [C][C]  WT[c][d]
    const float* __restrict__ gw,
    const float* __restrict__ bw,
    const int* __restrict__ idx,
    float* __restrict__ out)
{
    const int b  = blockIdx.z;
    const int m0 = blockIdx.y * BM;  // p
    const int n0 = blockIdx.x * BN;  // d
    const float* A = Zm + (size_t)b * PP * CC;   // lda = 256

    __shared__ float As[BK][BM + 4];
    __shared__ float Bs[BK][BN];

    const int t  = threadIdx.x;
    const int tx = t & 15;
    const int ty = t >> 4;

    float acc[TM][TN];
    #pragma unroll
    for (int i = 0; i < TM; i++)
        #pragma unroll
        for (int j = 0; j < TN; j++) acc[i][j] = 0.0f;

    for (int k0 = 0; k0 < CC; k0 += BK) {
        {
            int l = t * 4;
            int m  = l >> 3;
            int kk = l & 7;
            float4 v = *(const float4*)(A + (size_t)(m0 + m) * CC + k0 + kk);
            As[kk + 0][m] = v.x;
            As[kk + 1][m] = v.y;
            As[kk + 2][m] = v.z;
            As[kk + 3][m] = v.w;
        }
        {
            int l = t * 4;
            int kk = l >> 7;
            int n  = l & 127;
            float4 v = *(const float4*)(WT + (size_t)(k0 + kk) * CC + n0 + n);
            *(float4*)&Bs[kk][n] = v;
        }
        __syncthreads();

        #pragma unroll
        for (int kk = 0; kk < BK; kk++) {
            float af[TM], bf[TN];
            #pragma unroll
            for (int i = 0; i < TM; i++) af[i] = As[kk][ty * TM + i];
            #pragma unroll
            for (int j = 0; j < TN; j++) bf[j] = Bs[kk][tx * TN + j];
            #pragma unroll
            for (int i = 0; i < TM; i++)
                #pragma unroll
                for (int j = 0; j < TN; j++)
                    acc[i][j] = fmaf(af[i], bf[j], acc[i][j]);
        }
        __syncthreads();
    }

    const float inv = rsqrtf(1.0f + 1e-5f);
    #pragma unroll
    for (int i = 0; i < TM; i++) {
        int p = m0 + ty * TM + i;
        int j = idx[b * PP + p];
        float* orow = out + (size_t)b * CC * HWN + j;
        #pragma unroll
        for (int jn = 0; jn < TN; jn++) {
            int d = n0 + tx * TN + jn;
            float v = fmaf(acc[i][jn], inv * gw[d], bw[d]);
            v = fmaxf(v, 0.0f);
            orow[(size_t)d * HWN] = v;
        }
    }
}

// ---------------------------------------------------------------
extern "C" void kernel_launch(void* const* d_in, const int* in_sizes, int n_in,
                              void* d_out, int out_size)
{
    const float* x        = (const float*)d_in[0];
    const float* edge     = (const float*)d_in[1];
    const float* wadj     = (const float*)d_in[2];
    const float* ga       = (const float*)d_in[3];
    const float* be       = (const float*)d_in[4];
    const float* wwg      = (const float*)d_in[5];
    const float* gw       = (const float*)d_in[6];
    const float* bw       = (const float*)d_in[7];
    float* out            = (float*)d_out;

    float *pG, *pZ, *pWT;
    int *pidx;
    cudaGetSymbolAddress((void**)&pG, g_G);
    cudaGetSymbolAddress((void**)&pZ, g_Z);
    cudaGetSymbolAddress((void**)&pWT, g_WT);
    cudaGetSymbolAddress((void**)&pidx, g_idx);

    cudaFuncSetAttribute(topk_kernel, cudaFuncAttributeMaxDynamicSharedMemorySize,
                         HWN * (int)sizeof(unsigned long long));

    // 1) out = x (scatter later overwrites selected columns)
    cudaMemcpyAsync(out, x, (size_t)BB * CC * HWN * sizeof(float),
                    cudaMemcpyDeviceToDevice, 0);

    // 2) top-2048 per batch (exact lax.top_k ordering)
    topk_kernel<<<BB, 1024, HWN * sizeof(unsigned long long)>>>(edge, pidx);

    // 3) gather G[b][p][c]
    {
        dim3 g(PP, BB);
        gather_kernel<<<g, CC>>>(x, pidx, pG);
    }

    // 4) transpose Wwg (tiny)
    transpose_wg<<<CC, CC>>>(wwg, pWT);

    // 5) GEMM1 + BN + ReLU + residual
    {
        dim3 g(CC / BN, PP / BM, BB);   // (2, 16, 4)
        gemm1_kernel<<<g, 256>>>(wadj, pG, ga, be, pZ);
    }

    // 6) GEMM2 + BN + ReLU + scatter into out
    {
        dim3 g(CC / BN, PP / BM, BB);   // (2, 16, 4)
        gemm2_kernel<<<g, 256>>>(pZ, pWT, gw, bw, pidx, out);
    }
}

// round 4
// speedup vs baseline: 2.3834x; 2.3834x over previous
#include <cuda_runtime.h>
#include <cuda_bf16.h>
#include <cstdint>

#define BB 4
#define CC 256
#define HWN 16384
#define PP 2048
#define THRV 0.8f

// ---------------- scratch (no allocations allowed) ----------------
__device__ __nv_bfloat16 g_Whi[PP * PP];          // Wadj bf16 hi [o][p]
__device__ __nv_bfloat16 g_Wlo[PP * PP];          // Wadj bf16 lo
__device__ __nv_bfloat16 g_Gthi[BB * CC * PP];    // G^T bf16 hi [b][c][p]
__device__ __nv_bfloat16 g_Gtlo[BB * CC * PP];
__device__ float         g_Gf[BB * PP * CC];      // G fp32 [b][p][c] (residual)
__device__ __nv_bfloat16 g_Zhi[BB * PP * CC];     // stage-1 out bf16 hi [b][p][c]
__device__ __nv_bfloat16 g_Zlo[BB * PP * CC];
__device__ __nv_bfloat16 g_WGhi[CC * CC];         // Wwg bf16 hi [d][c]
__device__ __nv_bfloat16 g_WGlo[CC * CC];
__device__ int           g_idx[BB * PP];

// ---------------- PTX helpers (baseline ISA only: sm_80+) ----------
__device__ __forceinline__ uint32_t smem_u32(const void* p) {
    uint32_t a;
    asm("{ .reg .u64 t; cvta.to.shared.u64 t, %1; cvt.u32.u64 %0, t; }" : "=r"(a) : "l"(p));
    return a;
}
#define CPA16(dst_u32, src_ptr) \
    asm volatile("cp.async.cg.shared.global [%0], [%1], 16;" :: "r"(dst_u32), "l"(src_ptr) : "memory")
#define CPA_COMMIT() asm volatile("cp.async.commit_group;" ::: "memory")
#define CPA_WAIT1()  asm volatile("cp.async.wait_group 1;" ::: "memory")

#define MMA_BF16(c, a0, a1, a2, a3, b0, b1) \
    asm volatile("mma.sync.aligned.m16n8k16.row.col.f32.bf16.bf16.f32 " \
        "{%0,%1,%2,%3}, {%4,%5,%6,%7}, {%8,%9}, {%0,%1,%2,%3};" \
        : "+f"((c)[0]), "+f"((c)[1]), "+f"((c)[2]), "+f"((c)[3]) \
        : "r"(a0), "r"(a1), "r"(a2), "r"(a3), "r"(b0), "r"(b1))

// ---------------- top-k: compact candidates then bitonic sort -------
__global__ void topk_kernel(const float* __restrict__ edge)
{
    extern __shared__ unsigned long long keys[];    // up to 8192
    __shared__ int cnt;
    const int b = blockIdx.x;
    const float* e = edge + b * HWN;
    if (threadIdx.x == 0) cnt = 0;
    __syncthreads();

    for (int i = threadIdx.x; i < HWN; i += blockDim.x) {
        float v = e[i];
        if (v >= THRV) {
            int pos = atomicAdd(&cnt, 1);
            if (pos < 8192)
                keys[pos] = ((unsigned long long)__float_as_uint(v) << 32) | (unsigned int)(~i);
        }
    }
    __syncthreads();
    int c = min(cnt, 8192);
    int n = (c <= 4096) ? 4096 : 8192;
    for (int i = c + threadIdx.x; i < n; i += blockDim.x) keys[i] = 0ull;
    __syncthreads();

    for (int k = 2; k <= n; k <<= 1) {
        for (int j = k >> 1; j > 0; j >>= 1) {
            for (int i = threadIdx.x; i < n; i += blockDim.x) {
                int ixj = i ^ j;
                if (ixj > i) {
                    unsigned long long a = keys[i], cc2 = keys[ixj];
                    bool up = (i & k) == 0;
                    if (up ? (a < cc2) : (a > cc2)) { keys[i] = cc2; keys[ixj] = a; }
                }
            }
            __syncthreads();
        }
    }
    for (int p = threadIdx.x; p < PP; p += blockDim.x)
        g_idx[b * PP + p] = (int)(~(unsigned int)(keys[p] & 0xFFFFFFFFu));
}

// ---------------- W preps: bf16 hi/lo splits ------------------------
__global__ void wprep_kernel(const float* __restrict__ W)
{
    for (size_t i = (size_t)blockIdx.x * blockDim.x + threadIdx.x;
         i < (size_t)PP * PP; i += (size_t)gridDim.x * blockDim.x) {
        float v = W[i];
        __nv_bfloat16 h = __float2bfloat16_rn(v);
        g_Whi[i] = h;
        g_Wlo[i] = __float2bfloat16_rn(v - __bfloat162float(h));
    }
}
__global__ void wgprep_kernel(const float* __restrict__ W)
{
    int i = blockIdx.x * blockDim.x + threadIdx.x;
    if (i < CC * CC) {
        float v = W[i];
        __nv_bfloat16 h = __float2bfloat16_rn(v);
        g_WGhi[i] = h;
        g_WGlo[i] = __float2bfloat16_rn(v - __bfloat162float(h));
    }
}

// ---------------- gather: x -> Gt bf16 hi/lo [c][p] + Gf fp32 [p][c]
__global__ void gather_kernel(const float* __restrict__ x)
{
    extern __shared__ float tile[];   // [64][257]
    __shared__ int jj[64];
    const int p0 = blockIdx.x * 64, b = blockIdx.y;
    if (threadIdx.x < 64) jj[threadIdx.x] = g_idx[b * PP + p0 + threadIdx.x];
    __syncthreads();

    for (int e = threadIdx.x; e < CC * 64; e += blockDim.x) {
        int c = e >> 6, pc = e & 63;
        tile[pc * 257 + c] = x[((size_t)b * CC + c) * HWN + jj[pc]];
    }
    __syncthreads();

    for (int e = threadIdx.x; e < CC * 64; e += blockDim.x) {
        int c = e >> 6, pc = e & 63;
        float v = tile[pc * 257 + c];
        __nv_bfloat16 h = __float2bfloat16_rn(v);
        size_t o = ((size_t)b * CC + c) * PP + p0 + pc;
        g_Gthi[o] = h;
        g_Gtlo[o] = __float2bfloat16_rn(v - __bfloat162float(h));
    }
    for (int e = threadIdx.x; e < 64 * CC; e += blockDim.x) {
        int pc = e >> 8, c = e & 255;
        g_Gf[((size_t)b * PP + p0 + pc) * CC + c] = tile[pc * 257 + c];
    }
}

// ---------------- mma.sync GEMM geometry ---------------------------
// CTA 128x128, BK=32 bf16, 256 thr, warps 2(m)x4(n), warp tile 64x32.
// smem stage: Ah,Al,Bh,Bl each [128][40] bf16 (80B rows, 16B-aligned,
// conflict-free for the m16n8k16 fragment LDS). STAGE = 40960B, 2 stages.
#define STAGE 40960
#define ROWE  40

#define FRAG_LOADS(sAh_, sAl_, sBh_, sBl_) \
    const int kb = kk * 16 + qid * 2; \
    uint32_t ah[4][4], al[4][4], bh[4][2], bl[4][2]; \
    _Pragma("unroll") \
    for (int mt = 0; mt < 4; mt++) { \
        int r = wm * 64 + mt * 16 + grp; \
        ah[mt][0] = *(const uint32_t*)((sAh_) + r * ROWE + kb); \
        ah[mt][1] = *(const uint32_t*)((sAh_) + (r + 8) * ROWE + kb); \
        ah[mt][2] = *(const uint32_t*)((sAh_) + r * ROWE + kb + 8); \
        ah[mt][3] = *(const uint32_t*)((sAh_) + (r + 8) * ROWE + kb + 8); \
        al[mt][0] = *(const uint32_t*)((sAl_) + r * ROWE + kb); \
        al[mt][1] = *(const uint32_t*)((sAl_) + (r + 8) * ROWE + kb); \
        al[mt][2] = *(const uint32_t*)((sAl_) + r * ROWE + kb + 8); \
        al[mt][3] = *(const uint32_t*)((sAl_) + (r + 8) * ROWE + kb + 8); \
    } \
    _Pragma("unroll") \
    for (int nt = 0; nt < 4; nt++) { \
        int rn = wn * 32 + nt * 8 + grp; \
        bh[nt][0] = *(const uint32_t*)((sBh_) + rn * ROWE + kb); \
        bh[nt][1] = *(const uint32_t*)((sBh_) + rn * ROWE + kb + 8); \
        bl[nt][0] = *(const uint32_t*)((sBl_) + rn * ROWE + kb); \
        bl[nt][1] = *(const uint32_t*)((sBl_) + rn * ROWE + kb + 8); \
    } \
    _Pragma("unroll") \
    for (int mt = 0; mt < 4; mt++) \
        _Pragma("unroll") \
        for (int nt = 0; nt < 4; nt++) { \
            MMA_BF16(acc[mt][nt], ah[mt][0], ah[mt][1], ah[mt][2], ah[mt][3], bh[nt][0], bh[nt][1]); \
            MMA_BF16(acc[mt][nt], al[mt][0], al[mt][1], al[mt][2], al[mt][3], bh[nt][0], bh[nt][1]); \
            MMA_BF16(acc[mt][nt], ah[mt][0], ah[mt][1], ah[mt][2], ah[mt][3], bl[nt][0], bl[nt][1]); \
        }

// ---------------- GEMM1: Z = relu(BN(W @ G)) + G --------------------
__global__ __launch_bounds__(256, 1) void gemm1_mma(
    const float* __restrict__ ga, const float* __restrict__ be)
{
    extern __shared__ __align__(16) char sm[];
    const uint32_t sb = smem_u32(sm);
    const int tid = threadIdx.x;
    const int b = blockIdx.z, m0 = blockIdx.y * 128, n0 = blockIdx.x * 128;
    const int lane = tid & 31, warp = tid >> 5;
    const int grp = lane >> 2, qid = lane & 3;
    const int wm = warp >> 2, wn = warp & 3;

    float acc[4][4][4];
    #pragma unroll
    for (int i = 0; i < 4; i++)
        #pragma unroll
        for (int j = 0; j < 4; j++)
            #pragma unroll
            for (int r = 0; r < 4; r++) acc[i][j][r] = 0.0f;

#define G1_FILL(st, k0) do { \
    uint32_t base_ = sb + (st) * STAGE; \
    for (int i_ = tid; i_ < 512; i_ += 256) { \
        int r_ = i_ >> 2, c8_ = (i_ & 3) * 8; \
        uint32_t d_ = base_ + r_ * 80 + c8_ * 2; \
        CPA16(d_,         g_Whi  + (size_t)(m0 + r_) * PP + (k0) + c8_); \
        CPA16(d_ + 10240, g_Wlo  + (size_t)(m0 + r_) * PP + (k0) + c8_); \
        CPA16(d_ + 20480, g_Gthi + ((size_t)b * CC + n0 + r_) * PP + (k0) + c8_); \
        CPA16(d_ + 30720, g_Gtlo + ((size_t)b * CC + n0 + r_) * PP + (k0) + c8_); \
    } } while (0)

    G1_FILL(0, 0);
    CPA_COMMIT();

    const int NIT = PP / 32;   // 64
    #pragma unroll 1
    for (int it = 0; it < NIT; it++) {
        if (it + 1 < NIT) G1_FILL((it + 1) & 1, (it + 1) * 32);
        CPA_COMMIT();
        CPA_WAIT1();
        __syncthreads();

        const __nv_bfloat16* sAh = (const __nv_bfloat16*)(sm + (it & 1) * STAGE);
        const __nv_bfloat16* sAl = sAh + 5120;
        const __nv_bfloat16* sBh = sAh + 10240;
        const __nv_bfloat16* sBl = sAh + 15360;

        #pragma unroll
        for (int kk = 0; kk < 2; kk++) {
            FRAG_LOADS(sAh, sAl, sBh, sBl)
        }
        __syncthreads();
    }

    const float inv = rsqrtf(1.0f + 1e-5f);
    #pragma unroll
    for (int mt = 0; mt < 4; mt++) {
        int row0 = m0 + wm * 64 + mt * 16 + grp;
        int row1 = row0 + 8;
        float s0 = inv * ga[row0], t0 = be[row0];
        float s1 = inv * ga[row1], t1 = be[row1];
        #pragma unroll
        for (int nt = 0; nt < 4; nt++) {
            int col = n0 + wn * 32 + nt * 8 + qid * 2;
            size_t o0 = ((size_t)b * PP + row0) * CC + col;
            size_t o1 = ((size_t)b * PP + row1) * CC + col;
            float2 gf0 = *(const float2*)(g_Gf + o0);
            float2 gf1 = *(const float2*)(g_Gf + o1);
            float v00 = fmaxf(fmaf(acc[mt][nt][0], s0, t0), 0.0f) + gf0.x;
            float v01 = fmaxf(fmaf(acc[mt][nt][1], s0, t0), 0.0f) + gf0.y;
            float v10 = fmaxf(fmaf(acc[mt][nt][2], s1, t1), 0.0f) + gf1.x;
            float v11 = fmaxf(fmaf(acc[mt][nt][3], s1, t1), 0.0f) + gf1.y;
            __nv_bfloat162 h0 = __floats2bfloat162_rn(v00, v01);
            __nv_bfloat162 h1 = __floats2bfloat162_rn(v10, v11);
            *(uint32_t*)(g_Zhi + o0) = *(uint32_t*)&h0;
            *(uint32_t*)(g_Zhi + o1) = *(uint32_t*)&h1;
            __nv_bfloat162 l0 = __floats2bfloat162_rn(v00 - __bfloat162float(h0.x),
                                                      v01 - __bfloat162float(h0.y));
            __nv_bfloat162 l1 = __floats2bfloat162_rn(v10 - __bfloat162float(h1.x),
                                                      v11 - __bfloat162float(h1.y));
            *(uint32_t*)(g_Zlo + o0) = *(uint32_t*)&l0;
            *(uint32_t*)(g_Zlo + o1) = *(uint32_t*)&l1;
        }
    }
#undef G1_FILL
}

// ---------------- GEMM2 + scatter -----------------------------------
__global__ __launch_bounds__(256, 1) void gemm2_mma(
    const float* __restrict__ gw, const float* __restrict__ bw,
    float* __restrict__ out)
{
    extern __shared__ __align__(16) char sm[];
    const uint32_t sb = smem_u32(sm);
    const int tid = threadIdx.x;
    const int b = blockIdx.z, m0 = blockIdx.y * 128, n0 = blockIdx.x * 128;
    const int lane = tid & 31, warp = tid >> 5;
    const int grp = lane >> 2, qid = lane & 3;
    const int wm = warp >> 2, wn = warp & 3;

    float acc[4][4][4];
    #pragma unroll
    for (int i = 0; i < 4; i++)
        #pragma unroll
        for (int j = 0; j < 4; j++)
            #pragma unroll
            for (int r = 0; r < 4; r++) acc[i][j][r] = 0.0f;

#define G2_FILL(st, k0) do { \
    uint32_t base_ = sb + (st) * STAGE; \
    for (int i_ = tid; i_ < 512; i_ += 256) { \
        int r_ = i_ >> 2, c8_ = (i_ & 3) * 8; \
        uint32_t d_ = base_ + r_ * 80 + c8_ * 2; \
        CPA16(d_,         g_Zhi  + ((size_t)b * PP + m0 + r_) * CC + (k0) + c8_); \
        CPA16(d_ + 10240, g_Zlo  + ((size_t)b * PP + m0 + r_) * CC + (k0) + c8_); \
        CPA16(d_ + 20480, g_WGhi + (size_t)(n0 + r_) * CC + (k0) + c8_); \
        CPA16(d_ + 30720, g_WGlo + (size_t)(n0 + r_) * CC + (k0) + c8_); \
    } } while (0)

    G2_FILL(0, 0);
    CPA_COMMIT();

    const int NIT = CC / 32;   // 8
    #pragma unroll 1
    for (int it = 0; it < NIT; it++) {
        if (it + 1 < NIT) G2_FILL((it + 1) & 1, (it + 1) * 32);
        CPA_COMMIT();
        CPA_WAIT1();
        __syncthreads();

        const __nv_bfloat16* sAh = (const __nv_bfloat16*)(sm + (it & 1) * STAGE);
        const __nv_bfloat16* sAl = sAh + 5120;
        const __nv_bfloat16* sBh = sAh + 10240;
        const __nv_bfloat16* sBl = sAh + 15360;

        #pragma unroll
        for (int kk = 0; kk < 2; kk++) {
            FRAG_LOADS(sAh, sAl, sBh, sBl)
        }
        __syncthreads();
    }

    const float inv = rsqrtf(1.0f + 1e-5f);
    int jr[8];
    #pragma unroll
    for (int mt = 0; mt < 4; mt++) {
        int row0 = m0 + wm * 64 + mt * 16 + grp;
        jr[mt * 2]     = g_idx[b * PP + row0];
        jr[mt * 2 + 1] = g_idx[b * PP + row0 + 8];
    }
    float* ob = out + (size_t)b * CC * HWN;
    #pragma unroll
    for (int nt = 0; nt < 4; nt++) {
        int col = n0 + wn * 32 + nt * 8 + qid * 2;
        float s0 = inv * gw[col],     t0 = bw[col];
        float s1 = inv * gw[col + 1], t1 = bw[col + 1];
        float* oc0 = ob + (size_t)col * HWN;
        float* oc1 = ob + (size_t)(col + 1) * HWN;
        #pragma unroll
        for (int mt = 0; mt < 4; mt++) {
            int j0 = jr[mt * 2], j1 = jr[mt * 2 + 1];
            oc0[j0] = fmaxf(fmaf(acc[mt][nt][0], s0, t0), 0.0f);
            oc1[j0] = fmaxf(fmaf(acc[mt][nt][1], s1, t1), 0.0f);
            oc0[j1] = fmaxf(fmaf(acc[mt][nt][2], s0, t0), 0.0f);
            oc1[j1] = fmaxf(fmaf(acc[mt][nt][3], s1, t1), 0.0f);
        }
    }
#undef G2_FILL
}

// ---------------------------------------------------------------
extern "C" void kernel_launch(void* const* d_in, const int* in_sizes, int n_in,
                              void* d_out, int out_size)
{
    const float* x    = (const float*)d_in[0];
    const float* edge = (const float*)d_in[1];
    const float* wadj = (const float*)d_in[2];
    const float* ga   = (const float*)d_in[3];
    const float* be   = (const float*)d_in[4];
    const float* wwg  = (const float*)d_in[5];
    const float* gw   = (const float*)d_in[6];
    const float* bw   = (const float*)d_in[7];
    float* out = (float*)d_out;

    cudaFuncSetAttribute(topk_kernel,   cudaFuncAttributeMaxDynamicSharedMemorySize, 8192 * 8);
    cudaFuncSetAttribute(gather_kernel, cudaFuncAttributeMaxDynamicSharedMemorySize, 64 * 257 * 4);
    cudaFuncSetAttribute(gemm1_mma,     cudaFuncAttributeMaxDynamicSharedMemorySize, 2 * STAGE);
    cudaFuncSetAttribute(gemm2_mma,     cudaFuncAttributeMaxDynamicSharedMemorySize, 2 * STAGE);

    // out = x (scatter later overwrites selected columns)
    cudaMemcpyAsync(out, x, (size_t)BB * CC * HWN * sizeof(float),
                    cudaMemcpyDeviceToDevice, 0);

    // weight preps (independent of data path)
    wprep_kernel<<<2048, 256>>>(wadj);
    wgprep_kernel<<<256, 256>>>(wwg);

    // top-2048 per batch (exact lax.top_k ordering)
    topk_kernel<<<BB, 1024, 8192 * 8>>>(edge);

    // gather (needs idx)
    {
        dim3 g(PP / 64, BB);
        gather_kernel<<<g, 256, 64 * 257 * 4>>>(x);
    }

    // GEMM1 + BN + ReLU + residual  (tensor cores via mma.sync)
    {
        dim3 g(CC / 128, PP / 128, BB);   // (2, 16, 4)
        gemm1_mma<<<g, 256, 2 * STAGE>>>(ga, be);
    }
    // GEMM2 + BN + ReLU + scatter
    {
        dim3 g(CC / 128, PP / 128, BB);   // (2, 16, 4)
        gemm2_mma<<<g, 256, 2 * STAGE>>>(gw, bw, out);
    }
}

// round 7
// speedup vs baseline: 3.0407x; 1.2758x over previous
#include <cuda_runtime.h>
#include <cuda_bf16.h>
#include <cstdint>

#define BB 4
#define CC 256
#define HWN 16384
#define PP 2048
#define THRV 0.8f

// ---------------- scratch (no allocations allowed) ----------------
__device__ __nv_bfloat16 g_Whi[PP * PP];          // Wadj bf16 hi [o][p]
__device__ __nv_bfloat16 g_Wlo[PP * PP];          // Wadj bf16 lo
__device__ __nv_bfloat16 g_Gthi[BB * CC * PP];    // G^T bf16 hi [b][c][p]
__device__ __nv_bfloat16 g_Gtlo[BB * CC * PP];
__device__ float         g_Gf[BB * PP * CC];      // G fp32 [b][p][c] (residual)
__device__ __nv_bfloat16 g_Zhi[BB * PP * CC];     // stage-1 out bf16 hi [b][p][c]
__device__ __nv_bfloat16 g_Zlo[BB * PP * CC];
__device__ __nv_bfloat16 g_WGhi[CC * CC];         // Wwg bf16 hi [d][c]
__device__ __nv_bfloat16 g_WGlo[CC * CC];
__device__ int           g_idx[BB * PP];

// ---------------- PTX helpers (baseline ISA: sm_80+) ---------------
__device__ __forceinline__ uint32_t smem_u32(const void* p) {
    uint32_t a;
    asm("{ .reg .u64 t; cvta.to.shared.u64 t, %1; cvt.u32.u64 %0, t; }" : "=r"(a) : "l"(p));
    return a;
}
#define CPA16(dst_u32, src_ptr) \
    asm volatile("cp.async.cg.shared.global [%0], [%1], 16;" :: "r"(dst_u32), "l"(src_ptr) : "memory")
#define CPA_COMMIT() asm volatile("cp.async.commit_group;" ::: "memory")
#define CPA_WAIT1()  asm volatile("cp.async.wait_group 1;" ::: "memory")

#define MMA_BF16(c, a0, a1, a2, a3, b0, b1) \
    asm volatile("mma.sync.aligned.m16n8k16.row.col.f32.bf16.bf16.f32 " \
        "{%0,%1,%2,%3}, {%4,%5,%6,%7}, {%8,%9}, {%0,%1,%2,%3};" \
        : "+f"((c)[0]), "+f"((c)[1]), "+f"((c)[2]), "+f"((c)[3]) \
        : "r"(a0), "r"(a1), "r"(a2), "r"(a3), "r"(b0), "r"(b1))

#define LDSM4(r0, r1, r2, r3, addr) \
    asm volatile("ldmatrix.sync.aligned.m8n8.x4.shared.b16 {%0,%1,%2,%3}, [%4];" \
        : "=r"(r0), "=r"(r1), "=r"(r2), "=r"(r3) : "r"(addr))

__device__ __forceinline__ uint32_t pack_hi2(float a, float b) {
    __nv_bfloat162 t = __floats2bfloat162_rn(a, b);
    return *(uint32_t*)&t;
}

// ---------------- fused prep: topk + W splits + out=x copy ----------
// blocks 0..3      : per-batch top-2048 (compact + bitonic), 64KB smem
// blocks 4..67     : Wadj bf16 hi/lo split (+ Wwg split)
// blocks 68..195   : copy out = x (float4)
__global__ __launch_bounds__(1024) void prep_kernel(
    const float* __restrict__ edge, const float* __restrict__ x,
    const float* __restrict__ wadj, const float* __restrict__ wwg,
    float* __restrict__ out)
{
    const int bid = blockIdx.x, tid = threadIdx.x;

    if (bid < 4) {                                // ---- topk ----
        extern __shared__ unsigned long long keys[];   // 8192 max
        __shared__ int cnt;
        const int b = bid;
        const float* e = edge + b * HWN;
        if (tid == 0) cnt = 0;
        __syncthreads();
        for (int i = tid; i < HWN; i += 1024) {
            float v = e[i];
            if (v >= THRV) {
                int pos = atomicAdd(&cnt, 1);
                if (pos < 8192)
                    keys[pos] = ((unsigned long long)__float_as_uint(v) << 32) | (unsigned int)(~i);
            }
        }
        __syncthreads();
        int c = min(cnt, 8192);
        int n = (c <= 4096) ? 4096 : 8192;
        for (int i = c + tid; i < n; i += 1024) keys[i] = 0ull;
        __syncthreads();
        for (int k = 2; k <= n; k <<= 1) {
            for (int j = k >> 1; j > 0; j >>= 1) {
                for (int i = tid; i < n; i += 1024) {
                    int ixj = i ^ j;
                    if (ixj > i) {
                        unsigned long long a = keys[i], cc2 = keys[ixj];
                        bool up = (i & k) == 0;
                        if (up ? (a < cc2) : (a > cc2)) { keys[i] = cc2; keys[ixj] = a; }
                    }
                }
                __syncthreads();
            }
        }
        for (int p = tid; p < PP; p += 1024)
            g_idx[b * PP + p] = (int)(~(unsigned int)(keys[p] & 0xFFFFFFFFu));
    } else if (bid < 68) {                        // ---- W splits ----
        const int gt = (bid - 4) * 1024 + tid;    // 65536 threads
        const float4* W4 = (const float4*)wadj;   // 1048576 float4
        for (int i = gt; i < PP * PP / 4; i += 64 * 1024) {
            float4 v = W4[i];
            __nv_bfloat16 h0 = __float2bfloat16_rn(v.x), h1 = __float2bfloat16_rn(v.y);
            __nv_bfloat16 h2 = __float2bfloat16_rn(v.z), h3 = __float2bfloat16_rn(v.w);
            uint2 hp, lp;
            hp.x = pack_hi2(v.x, v.y); hp.y = pack_hi2(v.z, v.w);
            lp.x = pack_hi2(v.x - __bfloat162float(h0), v.y - __bfloat162float(h1));
            lp.y = pack_hi2(v.z - __bfloat162float(h2), v.w - __bfloat162float(h3));
            *(uint2*)(g_Whi + (size_t)i * 4) = hp;
            *(uint2*)(g_Wlo + (size_t)i * 4) = lp;
        }
        const float4* G4 = (const float4*)wwg;    // 16384 float4
        if (gt < CC * CC / 4) {
            float4 v = G4[gt];
            __nv_bfloat16 h0 = __float2bfloat16_rn(v.x), h1 = __float2bfloat16_rn(v.y);
            __nv_bfloat16 h2 = __float2bfloat16_rn(v.z), h3 = __float2bfloat16_rn(v.w);
            uint2 hp, lp;
            hp.x = pack_hi2(v.x, v.y); hp.y = pack_hi2(v.z, v.w);
            lp.x = pack_hi2(v.x - __bfloat162float(h0), v.y - __bfloat162float(h1));
            lp.y = pack_hi2(v.z - __bfloat162float(h2), v.w - __bfloat162float(h3));
            *(uint2*)(g_WGhi + (size_t)gt * 4) = hp;
            *(uint2*)(g_WGlo + (size_t)gt * 4) = lp;
        }
    } else {                                      // ---- out = x ----
        const int gt = (bid - 68) * 1024 + tid;   // 131072 threads
        const float4* X4 = (const float4*)x;
        float4* O4 = (float4*)out;
        const int NT = BB * CC * HWN / 4;         // 4194304
        for (int i = gt; i < NT; i += 128 * 1024)
            O4[i] = X4[i];
    }
}

// ---------------- gather: x -> Gt bf16 hi/lo [c][p] + Gf fp32 [p][c]
// grid (PP/64, CC/64, BB), 256 threads; tile 64p x 64c
__global__ __launch_bounds__(256) void gather_kernel(const float* __restrict__ x)
{
    __shared__ float tile[64][65];
    __shared__ int jj[64];
    const int p0 = blockIdx.x * 64, c0 = blockIdx.y * 64, b = blockIdx.z;
    const int tid = threadIdx.x;
    if (tid < 64) jj[tid] = g_idx[b * PP + p0 + tid];
    __syncthreads();

    // 16 independent scattered loads per thread
    #pragma unroll
    for (int e = tid; e < 64 * 64; e += 256) {
        int pc = e & 63, cl = e >> 6;
        tile[pc][cl] = x[((size_t)b * CC + c0 + cl) * HWN + jj[pc]];
    }
    __syncthreads();

    // Gt [c][p] bf16 hi/lo, coalesced over p
    #pragma unroll
    for (int e = tid; e < 64 * 64; e += 256) {
        int cl = e >> 6, pc = e & 63;
        float v = tile[pc][cl];
        __nv_bfloat16 h = __float2bfloat16_rn(v);
        size_t o = ((size_t)b * CC + c0 + cl) * PP + p0 + pc;
        g_Gthi[o] = h;
        g_Gtlo[o] = __float2bfloat16_rn(v - __bfloat162float(h));
    }
    // Gf [p][c] fp32, coalesced over c
    #pragma unroll
    for (int e = tid; e < 64 * 64; e += 256) {
        int pc = e >> 6, cl = e & 63;
        g_Gf[((size_t)b * PP + p0 + pc) * CC + c0 + cl] = tile[pc][cl];
    }
}

// ---------------- mma.sync GEMM geometry ---------------------------
// CTA 128(M) x 64(N), BK=32, 256 thr, warps 2(m) x 4(n), warp 64x16.
// smem stage: Ah/Al [128][40], Bh/Bl [64][40] bf16; 80B padded rows.
// STAGE = 10240*2 + 5120*2 = 30720 B, 2 stages.
#define STAGE 30720
#define ROWE  40

// ---------------- GEMM1: Z = relu(BN(W @ G)) + G --------------------
__global__ __launch_bounds__(256, 2) void gemm1_mma(
    const float* __restrict__ ga, const float* __restrict__ be)
{
    extern __shared__ __align__(16) char sm[];
    const uint32_t sb = smem_u32(sm);
    const int tid = threadIdx.x;
    const int b = blockIdx.z, m0 = blockIdx.y * 128, n0 = blockIdx.x * 64;
    const int lane = tid & 31, warp = tid >> 5;
    const int grp = lane >> 2, qid = lane & 3;
    const int wm = warp >> 2, wn = warp & 3;

    float acc[4][2][4];
    #pragma unroll
    for (int i = 0; i < 4; i++)
        #pragma unroll
        for (int j = 0; j < 2; j++)
            #pragma unroll
            for (int r = 0; r < 4; r++) acc[i][j][r] = 0.0f;

#define G1_FILL(st, k0) do { \
    uint32_t base_ = sb + (st) * STAGE; \
    for (int i_ = tid; i_ < 512; i_ += 256) { \
        int r_ = i_ >> 2, c8_ = (i_ & 3) * 8; \
        uint32_t d_ = base_ + r_ * 80 + c8_ * 2; \
        CPA16(d_,         g_Whi + (size_t)(m0 + r_) * PP + (k0) + c8_); \
        CPA16(d_ + 10240, g_Wlo + (size_t)(m0 + r_) * PP + (k0) + c8_); \
    } \
    { \
        int i_ = tid; \
        int r_ = i_ >> 2, c8_ = (i_ & 3) * 8; \
        uint32_t d_ = base_ + 20480 + r_ * 80 + c8_ * 2; \
        CPA16(d_,        g_Gthi + ((size_t)b * CC + n0 + r_) * PP + (k0) + c8_); \
        CPA16(d_ + 5120, g_Gtlo + ((size_t)b * CC + n0 + r_) * PP + (k0) + c8_); \
    } } while (0)

    G1_FILL(0, 0);
    CPA_COMMIT();

    const int NIT = PP / 32;   // 64
    #pragma unroll 1
    for (int it = 0; it < NIT; it++) {
        if (it + 1 < NIT) G1_FILL((it + 1) & 1, (it + 1) * 32);
        CPA_COMMIT();
        CPA_WAIT1();
        __syncthreads();

        const uint32_t stb = sb + (it & 1) * STAGE;
        #pragma unroll
        for (int kk = 0; kk < 2; kk++) {
            const int kb0 = kk * 16;
            uint32_t ah[4][4], al[4][4], bh[4], bl[4];
            #pragma unroll
            for (int mt = 0; mt < 4; mt++) {
                uint32_t aaddr = stb + ((wm * 64 + mt * 16 + (lane & 15)) * ROWE
                                        + kb0 + ((lane >> 4) << 3)) * 2;
                LDSM4(ah[mt][0], ah[mt][1], ah[mt][2], ah[mt][3], aaddr);
                LDSM4(al[mt][0], al[mt][1], al[mt][2], al[mt][3], aaddr + 10240);
            }
            {
                uint32_t baddr = stb + 20480
                    + ((wn * 16 + ((lane >> 4) << 3) + (lane & 7)) * ROWE
                       + kb0 + (((lane >> 3) & 1) << 3)) * 2;
                LDSM4(bh[0], bh[1], bh[2], bh[3], baddr);
                LDSM4(bl[0], bl[1], bl[2], bl[3], baddr + 5120);
            }
            #pragma unroll
            for (int mt = 0; mt < 4; mt++)
                #pragma unroll
                for (int nt = 0; nt < 2; nt++) {
                    MMA_BF16(acc[mt][nt], ah[mt][0], ah[mt][1], ah[mt][2], ah[mt][3],
                             bh[nt * 2], bh[nt * 2 + 1]);
                    MMA_BF16(acc[mt][nt], al[mt][0], al[mt][1], al[mt][2], al[mt][3],
                             bh[nt * 2], bh[nt * 2 + 1]);
                    MMA_BF16(acc[mt][nt], ah[mt][0], ah[mt][1], ah[mt][2], ah[mt][3],
                             bl[nt * 2], bl[nt * 2 + 1]);
                }
        }
        __syncthreads();
    }

    const float inv = rsqrtf(1.0f + 1e-5f);
    #pragma unroll
    for (int mt = 0; mt < 4; mt++) {
        int row0 = m0 + wm * 64 + mt * 16 + grp;
        int row1 = row0 + 8;
        float s0 = inv * ga[row0], t0 = be[row0];
        float s1 = inv * ga[row1], t1 = be[row1];
        #pragma unroll
        for (int nt = 0; nt < 2; nt++) {
            int col = n0 + wn * 16 + nt * 8 + qid * 2;
            size_t o0 = ((size_t)b * PP + row0) * CC + col;
            size_t o1 = ((size_t)b * PP + row1) * CC + col;
            float2 gf0 = *(const float2*)(g_Gf + o0);
            float2 gf1 = *(const float2*)(g_Gf + o1);
            float v00 = fmaxf(fmaf(acc[mt][nt][0], s0, t0), 0.0f) + gf0.x;
            float v01 = fmaxf(fmaf(acc[mt][nt][1], s0, t0), 0.0f) + gf0.y;
            float v10 = fmaxf(fmaf(acc[mt][nt][2], s1, t1), 0.0f) + gf1.x;
            float v11 = fmaxf(fmaf(acc[mt][nt][3], s1, t1), 0.0f) + gf1.y;
            __nv_bfloat162 h0 = __floats2bfloat162_rn(v00, v01);
            __nv_bfloat162 h1 = __floats2bfloat162_rn(v10, v11);
            *(uint32_t*)(g_Zhi + o0) = *(uint32_t*)&h0;
            *(uint32_t*)(g_Zhi + o1) = *(uint32_t*)&h1;
            __nv_bfloat162 l0 = __floats2bfloat162_rn(v00 - __bfloat162float(h0.x),
                                                      v01 - __bfloat162float(h0.y));
            __nv_bfloat162 l1 = __floats2bfloat162_rn(v10 - __bfloat162float(h1.x),
                                                      v11 - __bfloat162float(h1.y));
            *(uint32_t*)(g_Zlo + o0) = *(uint32_t*)&l0;
            *(uint32_t*)(g_Zlo + o1) = *(uint32_t*)&l1;
        }
    }
#undef G1_FILL
}

// ---------------- GEMM2 + scatter -----------------------------------
__global__ __launch_bounds__(256, 2) void gemm2_mma(
    const float* __restrict__ gw, const float* __restrict__ bw,
    float* __restrict__ out)
{
    extern __shared__ __align__(16) char sm[];
    const uint32_t sb = smem_u32(sm);
    const int tid = threadIdx.x;
    const int b = blockIdx.z, m0 = blockIdx.y * 128, n0 = blockIdx.x * 64;
    const int lane = tid & 31, warp = tid >> 5;
    const int grp = lane >> 2, qid = lane & 3;
    const int wm = warp >> 2, wn = warp & 3;

    float acc[4][2][4];
    #pragma unroll
    for (int i = 0; i < 4; i++)
        #pragma unroll
        for (int j = 0; j < 2; j++)
            #pragma unroll
            for (int r = 0; r < 4; r++) acc[i][j][r] = 0.0f;

#define G2_FILL(st, k0) do { \
    uint32_t base_ = sb + (st) * STAGE; \
    for (int i_ = tid; i_ < 512; i_ += 256) { \
        int r_ = i_ >> 2, c8_ = (i_ & 3) * 8; \
        uint32_t d_ = base_ + r_ * 80 + c8_ * 2; \
        CPA16(d_,         g_Zhi + ((size_t)b * PP + m0 + r_) * CC + (k0) + c8_); \
        CPA16(d_ + 10240, g_Zlo + ((size_t)b * PP + m0 + r_) * CC + (k0) + c8_); \
    } \
    { \
        int i_ = tid; \
        int r_ = i_ >> 2, c8_ = (i_ & 3) * 8; \
        uint32_t d_ = base_ + 20480 + r_ * 80 + c8_ * 2; \
        CPA16(d_,        g_WGhi + (size_t)(n0 + r_) * CC + (k0) + c8_); \
        CPA16(d_ + 5120, g_WGlo + (size_t)(n0 + r_) * CC + (k0) + c8_); \
    } } while (0)

    G2_FILL(0, 0);
    CPA_COMMIT();

    const int NIT = CC / 32;   // 8
    #pragma unroll 1
    for (int it = 0; it < NIT; it++) {
        if (it + 1 < NIT) G2_FILL((it + 1) & 1, (it + 1) * 32);
        CPA_COMMIT();
        CPA_WAIT1();
        __syncthreads();

        const uint32_t stb = sb + (it & 1) * STAGE;
        #pragma unroll
        for (int kk = 0; kk < 2; kk++) {
            const int kb0 = kk * 16;
            uint32_t ah[4][4], al[4][4], bh[4], bl[4];
            #pragma unroll
            for (int mt = 0; mt < 4; mt++) {
                uint32_t aaddr = stb + ((wm * 64 + mt * 16 + (lane & 15)) * ROWE
                                        + kb0 + ((lane >> 4) << 3)) * 2;
                LDSM4(ah[mt][0], ah[mt][1], ah[mt][2], ah[mt][3], aaddr);
                LDSM4(al[mt][0], al[mt][1], al[mt][2], al[mt][3], aaddr + 10240);
            }
            {
                uint32_t baddr = stb + 20480
                    + ((wn * 16 + ((lane >> 4) << 3) + (lane & 7)) * ROWE
                       + kb0 + (((lane >> 3) & 1) << 3)) * 2;
                LDSM4(bh[0], bh[1], bh[2], bh[3], baddr);
                LDSM4(bl[0], bl[1], bl[2], bl[3], baddr + 5120);
            }
            #pragma unroll
            for (int mt = 0; mt < 4; mt++)
                #pragma unroll
                for (int nt = 0; nt < 2; nt++) {
                    MMA_BF16(acc[mt][nt], ah[mt][0], ah[mt][1], ah[mt][2], ah[mt][3],
                             bh[nt * 2], bh[nt * 2 + 1]);
                    MMA_BF16(acc[mt][nt], al[mt][0], al[mt][1], al[mt][2], al[mt][3],
                             bh[nt * 2], bh[nt * 2 + 1]);
                    MMA_BF16(acc[mt][nt], ah[mt][0], ah[mt][1], ah[mt][2], ah[mt][3],
                             bl[nt * 2], bl[nt * 2 + 1]);
                }
        }
        __syncthreads();
    }

    const float inv = rsqrtf(1.0f + 1e-5f);
    int jr[8];
    #pragma unroll
    for (int mt = 0; mt < 4; mt++) {
        int row0 = m0 + wm * 64 + mt * 16 + grp;
        jr[mt * 2]     = g_idx[b * PP + row0];
        jr[mt * 2 + 1] = g_idx[b * PP + row0 + 8];
    }
    float* ob = out + (size_t)b * CC * HWN;
    #pragma unroll
    for (int nt = 0; nt < 2; nt++) {
        int col = n0 + wn * 16 + nt * 8 + qid * 2;
        float s0 = inv * gw[col],     t0 = bw[col];
        float s1 = inv * gw[col + 1], t1 = bw[col + 1];
        float* oc0 = ob + (size_t)col * HWN;
        float* oc1 = ob + (size_t)(col + 1) * HWN;
        #pragma unroll
        for (int mt = 0; mt < 4; mt++) {
            int j0 = jr[mt * 2], j1 = jr[mt * 2 + 1];
            oc0[j0] = fmaxf(fmaf(acc[mt][nt][0], s0, t0), 0.0f);
            oc1[j0] = fmaxf(fmaf(acc[mt][nt][1], s1, t1), 0.0f);
            oc0[j1] = fmaxf(fmaf(acc[mt][nt][2], s0, t0), 0.0f);
            oc1[j1] = fmaxf(fmaf(acc[mt][nt][3], s1, t1), 0.0f);
        }
    }
#undef G2_FILL
}

// ---------------------------------------------------------------
extern "C" void kernel_launch(void* const* d_in, const int* in_sizes, int n_in,
                              void* d_out, int out_size)
{
    const float* x    = (const float*)d_in[0];
    const float* edge = (const float*)d_in[1];
    const float* wadj = (const float*)d_in[2];
    const float* ga   = (const float*)d_in[3];
    const float* be   = (const float*)d_in[4];
    const float* wwg  = (const float*)d_in[5];
    const float* gw   = (const float*)d_in[6];
    const float* bw   = (const float*)d_in[7];
    float* out = (float*)d_out;

    cudaFuncSetAttribute(prep_kernel, cudaFuncAttributeMaxDynamicSharedMemorySize, 65536);
    cudaFuncSetAttribute(gemm1_mma,   cudaFuncAttributeMaxDynamicSharedMemorySize, 2 * STAGE);
    cudaFuncSetAttribute(gemm2_mma,   cudaFuncAttributeMaxDynamicSharedMemorySize, 2 * STAGE);

    // fused: topk (blocks 0-3) + W splits (4-67) + out=x copy (68-195)
    prep_kernel<<<196, 1024, 65536>>>(edge, x, wadj, wwg, out);

    // gather (needs idx)
    {
        dim3 g(PP / 64, CC / 64, BB);   // (32, 4, 4)
        gather_kernel<<<g, 256>>>(x);
    }

    // GEMM1 + BN + ReLU + residual
    {
        dim3 g(CC / 64, PP / 128, BB);  // (4, 16, 4)
        gemm1_mma<<<g, 256, 2 * STAGE>>>(ga, be);
    }
    // GEMM2 + BN + ReLU + scatter
    {
        dim3 g(CC / 64, PP / 128, BB);  // (4, 16, 4)
        gemm2_mma<<<g, 256, 2 * STAGE>>>(gw, bw, out);
    }
}